// round 14
// baseline (speedup 1.0000x reference)
#include <cuda_runtime.h>
#include <cuda_fp16.h>
#include <math.h>

#define BB   8
#define NN   1024
#define FF   128
#define HH   8
#define MAXN 256
#define PRED_IN 384
#define LDIM 2
#define ASTRIDE 136   // fp16 smem row stride

// ---------------- device scratch ----------------
__device__ int    g_nbr[BB * NN * MAXN];
__device__ int    g_cnt[BB * NN];
__device__ int    g_qoff[BB * NN * 4];
__device__ __half g_hp16[(size_t)BB * HH * NN * FF];     // 16 MB
__device__ float  g_s[BB * HH * NN];
__device__ float  g_d[BB * HH * NN];
__device__ uint2  g_ep[(size_t)BB * HH * NN * 2 * 256];  // padded halves
__device__ __half g_po2h[(size_t)2 * BB * HH * NN * FF]; // 33 MB fp16 partials
__device__ float  g_x1[BB * NN * FF];
__device__ float  g_x2[BB * NN * FF];
__device__ float  g_x3[BB * NN * FF];
__device__ float  g_pmax[BB * 8 * PRED_IN];

__device__ __forceinline__ float tanh_fast(float x) {
    float y;
    asm("tanh.approx.f32 %0, %1;" : "=f"(y) : "f"(x));
    return y;
}

// ---------------- K1: adjacency -> neighbor lists + quartile offsets -------
__global__ __launch_bounds__(256) void build_nbr(const float* __restrict__ adj) {
    int wgl  = blockIdx.x * 8 + (threadIdx.x >> 5);
    int lane = threadIdx.x & 31;
    int b = wgl / NN;
    int i = wgl % NN;
    const float* row = adj + (size_t)(b * NN + i) * NN;
    int base = 0;
    int qof[4];
    for (int c = 0; c < NN; c += 32) {
        float v = row[c + lane];
        unsigned m = __ballot_sync(0xffffffffu, v > 0.0f);
        if (v > 0.0f) {
            int pos = base + __popc(m & ((1u << lane) - 1u));
            if (pos < MAXN) g_nbr[(b * NN + i) * MAXN + pos] = c + lane;
        }
        base += __popc(m);
        if (((c + 32) & 255) == 0)
            qof[((c + 32) >> 8) - 1] = min(base, MAXN);
    }
    if (lane == 0) {
        g_cnt[b * NN + i] = min(base, MAXN);
        *(int4*)&g_qoff[(b * NN + i) * 4] =
            make_int4(qof[0], qof[1], qof[2], qof[3]);
    }
}

// ---------------- K2: fp16 tensor-core GEMM + fused tanh-dot epilogue ------
#define MMA16816(d, a, b) asm volatile( \
    "mma.sync.aligned.m16n8k16.row.col.f32.f16.f16.f32 " \
    "{%0,%1,%2,%3}, {%4,%5,%6,%7}, {%8,%9}, {%0,%1,%2,%3};" \
    : "+f"(d[0]), "+f"(d[1]), "+f"(d[2]), "+f"(d[3]) \
    : "r"(a[0]), "r"(a[1]), "r"(a[2]), "r"(a[3]), "r"(b[0]), "r"(b[1]))

__global__ __launch_bounds__(256) void gat_gemm(const float* __restrict__ x,
                                                const float* __restrict__ w,
                                                const float* __restrict__ asrc,
                                                const float* __restrict__ adst) {
    extern __shared__ __align__(16) char dynsm[];
    __half* A_s  = (__half*)dynsm;                          // [128][136]
    __half* Bt_s = (__half*)(dynsm + 128 * ASTRIDE * 2);    // [128][136]
    float*  redS = (float*)(dynsm + 2 * 128 * ASTRIDE * 2); // [128][2]
    float*  redD = redS + 256;
    float*  sa   = redD + 256;
    float*  da   = sa + 128;

    const int mt  = blockIdx.x;
    const int h   = blockIdx.y;
    const int b   = mt >> 3;
    const int n0m = (mt & 7) * 128;
    const int bh  = b * HH + h;

    const int tid  = threadIdx.x;
    const int warp = tid >> 5;
    const int lane = tid & 31;
    const int wm   = warp & 3;
    const int wn   = warp >> 2;
    const int g    = lane >> 2;
    const int tq   = lane & 3;

    if (tid < FF) { sa[tid] = asrc[h * FF + tid]; da[tid] = adst[h * FF + tid]; }

    const float* xb = x + (size_t)(b * NN + n0m) * FF;
#pragma unroll
    for (int it = 0; it < 16; it++) {
        int idx = tid + it * 256;
        int row = idx >> 5;
        int kq  = (idx & 31) * 4;
        float4 v = *(const float4*)&xb[(size_t)row * FF + kq];
        *(__half2*)&A_s[row * ASTRIDE + kq]     = __floats2half2_rn(v.x, v.y);
        *(__half2*)&A_s[row * ASTRIDE + kq + 2] = __floats2half2_rn(v.z, v.w);
    }
    const float* wh = w + (size_t)h * FF * FF;
#pragma unroll
    for (int it = 0; it < 16; it++) {
        int idx = tid + it * 256;
        int k  = idx >> 5;
        int nq = (idx & 31) * 4;
        float4 v = *(const float4*)&wh[(size_t)k * FF + nq];
        Bt_s[(nq + 0) * ASTRIDE + k] = __float2half_rn(v.x);
        Bt_s[(nq + 1) * ASTRIDE + k] = __float2half_rn(v.y);
        Bt_s[(nq + 2) * ASTRIDE + k] = __float2half_rn(v.z);
        Bt_s[(nq + 3) * ASTRIDE + k] = __float2half_rn(v.w);
    }
    __syncthreads();

    float acc[2][8][4];
#pragma unroll
    for (int m = 0; m < 2; m++)
#pragma unroll
        for (int n = 0; n < 8; n++)
#pragma unroll
            for (int c = 0; c < 4; c++) acc[m][n][c] = 0.0f;

    const int m0w = wm * 32;
    const int n0w = wn * 64;

#pragma unroll
    for (int ks = 0; ks < 8; ks++) {
        const int kc = ks * 16;
        unsigned a[2][4], bf[8][2];
#pragma unroll
        for (int m = 0; m < 2; m++) {
            int r0 = (m0w + m * 16 + g) * ASTRIDE + kc + tq * 2;
            a[m][0] = *(const unsigned*)&A_s[r0];
            a[m][1] = *(const unsigned*)&A_s[r0 + 8 * ASTRIDE];
            a[m][2] = *(const unsigned*)&A_s[r0 + 8];
            a[m][3] = *(const unsigned*)&A_s[r0 + 8 * ASTRIDE + 8];
        }
#pragma unroll
        for (int n = 0; n < 8; n++) {
            int rb = (n0w + n * 8 + g) * ASTRIDE + kc + tq * 2;
            bf[n][0] = *(const unsigned*)&Bt_s[rb];
            bf[n][1] = *(const unsigned*)&Bt_s[rb + 8];
        }
#pragma unroll
        for (int m = 0; m < 2; m++)
#pragma unroll
            for (int n = 0; n < 8; n++)
                MMA16816(acc[m][n], a[m], bf[n]);
    }
    __syncthreads();

    float sp[2][2], dp[2][2];
#pragma unroll
    for (int m = 0; m < 2; m++)
#pragma unroll
        for (int rh = 0; rh < 2; rh++) { sp[m][rh] = 0.0f; dp[m][rh] = 0.0f; }

#pragma unroll
    for (int m = 0; m < 2; m++)
#pragma unroll
        for (int n = 0; n < 8; n++)
#pragma unroll
            for (int c = 0; c < 4; c++) {
                const int rh  = c >> 1;
                const int row = m0w + m * 16 + g + rh * 8;
                const int col = n0w + n * 8 + tq * 2 + (c & 1);
                const float v = acc[m][n][c];
                A_s[row * ASTRIDE + col] = __float2half_rn(v);
                const float t = tanh_fast(v);
                sp[m][rh] = fmaf(t, sa[col], sp[m][rh]);
                dp[m][rh] = fmaf(t, da[col], dp[m][rh]);
            }
#pragma unroll
    for (int m = 0; m < 2; m++)
#pragma unroll
        for (int rh = 0; rh < 2; rh++) {
            float s = sp[m][rh], d = dp[m][rh];
            s += __shfl_xor_sync(0xffffffffu, s, 1);
            s += __shfl_xor_sync(0xffffffffu, s, 2);
            d += __shfl_xor_sync(0xffffffffu, d, 1);
            d += __shfl_xor_sync(0xffffffffu, d, 2);
            if (tq == 0) {
                const int row = m0w + m * 16 + g + rh * 8;
                redS[row * 2 + wn] = s;
                redD[row * 2 + wn] = d;
            }
        }
    __syncthreads();

    __half* hpo = g_hp16 + ((size_t)bh * NN + n0m) * FF;
#pragma unroll
    for (int it = 0; it < 8; it++) {
        int idx = tid + it * 256;
        int row = idx >> 4;
        int seg = (idx & 15) * 8;
        *(uint4*)&hpo[(size_t)row * FF + seg] =
            *(const uint4*)&A_s[row * ASTRIDE + seg];
    }
    if (tid < 128) {
        g_s[bh * NN + n0m + tid] = redS[tid * 2] + redS[tid * 2 + 1];
        g_d[bh * NN + n0m + tid] = redD[tid * 2] + redD[tid * 2 + 1];
    }
}

// ---------------- K3a: attention weights -> padded per-half segments -------
__global__ __launch_bounds__(256) void attn_weights() {
    const int wg   = blockIdx.x * 8 + (threadIdx.x >> 5);
    const int lane = threadIdx.x & 31;
    const int h  = wg & 7;
    const int ri = wg >> 3;
    const int b  = ri >> 10;
    const int i  = ri & 1023;
    const int bh = b * HH + h;

    const int cnt = g_cnt[b * NN + i];
    const int qy  = g_qoff[(b * NN + i) * 4 + 1];   // edges with j < 512
    const int* nb = &g_nbr[(b * NN + i) * MAXN];
    const float* dd = g_d + bh * NN;
    const float  si = g_s[bh * NN + i];
    uint2* ep0 = &g_ep[((size_t)(bh * NN + i) * 2) * 256];
    uint2* ep1 = ep0 + 256;

    float m = -1e30f;
    float scv[8];
    int   jv[8];
#pragma unroll
    for (int t = 0; t < 8; t++) {
        int k = lane + t * 32;
        float sc = -1e30f;
        int j = 0;
        if (k < cnt) {
            j = nb[k];
            sc = si + dd[j];
            sc = sc >= 0.0f ? sc : 0.2f * sc;
        }
        jv[t] = j;
        scv[t] = sc;
        m = fmaxf(m, sc);
    }
#pragma unroll
    for (int off = 16; off > 0; off >>= 1)
        m = fmaxf(m, __shfl_xor_sync(0xffffffffu, m, off));

    float ssum = 0.0f;
    float ev[8];
#pragma unroll
    for (int t = 0; t < 8; t++) {
        int k = lane + t * 32;
        float e = 0.0f;
        if (k < cnt) e = __expf(scv[t] - m);
        ev[t] = e;
        ssum += e;
    }
#pragma unroll
    for (int off = 16; off > 0; off >>= 1)
        ssum += __shfl_xor_sync(0xffffffffu, ssum, off);
    const float wsc = (1.0f / (float)HH) / ssum;

#pragma unroll
    for (int t = 0; t < 8; t++) {
        int k = lane + t * 32;
        if (k < cnt) {
            uint2 e = make_uint2((unsigned)((jv[t] & 511) << 8),
                                 __float_as_uint(ev[t] * wsc));
            if (k < qy) ep0[k] = e;
            else        ep1[k - qy] = e;
        }
    }
    const int len1 = cnt - qy;
    const int p0 = (qy + 7) & ~7;
    const int p1 = (len1 + 7) & ~7;
    if (qy + lane < p0)   ep0[qy + lane]   = make_uint2(0u, 0u);
    if (len1 + lane < p1) ep1[len1 + lane] = make_uint2(0u, 0u);
}

// ---------------- K3b: half-owned fp16 smem gather (uint4 edge loads) ------
__global__ __launch_bounds__(1024) void gat_gather() {
    extern __shared__ __align__(16) char hpb[];   // [512][128] fp16 = 128 KB
    const int q   = blockIdx.x;           // 0..1
    const int h   = blockIdx.y;
    const int b   = blockIdx.z;
    const int tid = threadIdx.x;
    const int w    = tid >> 5;
    const int lane = tid & 31;
    const int group = lane >> 4;
    const int gl    = lane & 15;
    const int bh  = b * HH + h;

    const __half* src = g_hp16 + ((size_t)bh * NN + q * 512) * FF;
#pragma unroll
    for (int it = 0; it < 8; it++) {
        int idx = tid + it * 1024;
        ((uint4*)hpb)[idx] = ((const uint4*)src)[idx];
    }
    __syncthreads();

    __half* po = g_po2h + ((size_t)q * BB * HH + bh) * NN * FF;
    const int gl16 = gl * 16;

#pragma unroll 1
    for (int ii = 0; ii < 16; ii++) {
        const int i = ii * 64 + w * 2 + group;
        const int qy  = g_qoff[(b * NN + i) * 4 + 1];
        const int cnt = g_cnt[b * NN + i];
        const int len = q ? (cnt - qy) : qy;
        const int n4  = ((len + 7) & ~7) >> 1;   // # of uint4 (2 edges each)
        const uint4* ep4 = (const uint4*)
            &g_ep[((size_t)(bh * NN + i) * 2 + q) * 256];

        float a0 = 0.f, a1 = 0.f, a2 = 0.f, a3 = 0.f;
        float a4 = 0.f, a5 = 0.f, a6 = 0.f, a7 = 0.f;
        for (int k0 = 0; k0 < n4; k0 += 4) {
            // 4 independent LDG.128 = 8 edges
            uint4 e0 = __ldg(ep4 + k0 + 0);
            uint4 e1 = __ldg(ep4 + k0 + 1);
            uint4 e2 = __ldg(ep4 + k0 + 2);
            uint4 e3 = __ldg(ep4 + k0 + 3);
#pragma unroll
            for (int t = 0; t < 4; t++) {
                const uint4 e = (t == 0) ? e0 : (t == 1) ? e1 :
                                (t == 2) ? e2 : e3;
                {
                    const float p = __uint_as_float(e.y);
                    uint4 hv = *(const uint4*)(hpb + e.x + gl16);
                    float2 f0 = __half22float2(*(__half2*)&hv.x);
                    float2 f1 = __half22float2(*(__half2*)&hv.y);
                    float2 f2 = __half22float2(*(__half2*)&hv.z);
                    float2 f3 = __half22float2(*(__half2*)&hv.w);
                    a0 = fmaf(p, f0.x, a0); a1 = fmaf(p, f0.y, a1);
                    a2 = fmaf(p, f1.x, a2); a3 = fmaf(p, f1.y, a3);
                    a4 = fmaf(p, f2.x, a4); a5 = fmaf(p, f2.y, a5);
                    a6 = fmaf(p, f3.x, a6); a7 = fmaf(p, f3.y, a7);
                }
                {
                    const float p = __uint_as_float(e.w);
                    uint4 hv = *(const uint4*)(hpb + e.z + gl16);
                    float2 f0 = __half22float2(*(__half2*)&hv.x);
                    float2 f1 = __half22float2(*(__half2*)&hv.y);
                    float2 f2 = __half22float2(*(__half2*)&hv.z);
                    float2 f3 = __half22float2(*(__half2*)&hv.w);
                    a0 = fmaf(p, f0.x, a0); a1 = fmaf(p, f0.y, a1);
                    a2 = fmaf(p, f1.x, a2); a3 = fmaf(p, f1.y, a3);
                    a4 = fmaf(p, f2.x, a4); a5 = fmaf(p, f2.y, a5);
                    a6 = fmaf(p, f3.x, a6); a7 = fmaf(p, f3.y, a7);
                }
            }
        }
        uint4 outv;
        *(__half2*)&outv.x = __floats2half2_rn(a0, a1);
        *(__half2*)&outv.y = __floats2half2_rn(a2, a3);
        *(__half2*)&outv.z = __floats2half2_rn(a4, a5);
        *(__half2*)&outv.w = __floats2half2_rn(a6, a7);
        *(uint4*)&po[(size_t)i * FF + gl * 8] = outv;
    }
}

// ---------------- K3c: reduce 2 halves x 8 heads + bias (+ReLU) ------------
__global__ __launch_bounds__(256) void head_reduce(const float* __restrict__ bias,
                                                   float* __restrict__ xout,
                                                   int do_relu) {
    const int idx = blockIdx.x * 256 + threadIdx.x;
    const int ig  = idx >> 4;
    const int c8  = idx & 15;
    const int b   = ig >> 10;
    const int i   = ig & 1023;

    float a[8];
#pragma unroll
    for (int c = 0; c < 8; c++) a[c] = 0.0f;
#pragma unroll
    for (int qh = 0; qh < 2 * HH; qh++) {
        const int q = qh >> 3;
        const int h = qh & 7;
        const uint4 v = *(const uint4*)
            &g_po2h[(((size_t)q * BB * HH + b * HH + h) * NN + i) * FF + c8 * 8];
        float2 f0 = __half22float2(*(__half2*)&v.x);
        float2 f1 = __half22float2(*(__half2*)&v.y);
        float2 f2 = __half22float2(*(__half2*)&v.z);
        float2 f3 = __half22float2(*(__half2*)&v.w);
        a[0] += f0.x; a[1] += f0.y; a[2] += f1.x; a[3] += f1.y;
        a[4] += f2.x; a[5] += f2.y; a[6] += f3.x; a[7] += f3.y;
    }
    const float4 b0 = *(const float4*)&bias[c8 * 8];
    const float4 b1 = *(const float4*)&bias[c8 * 8 + 4];
    a[0] += b0.x; a[1] += b0.y; a[2] += b0.z; a[3] += b0.w;
    a[4] += b1.x; a[5] += b1.y; a[6] += b1.z; a[7] += b1.w;
    if (do_relu)
#pragma unroll
        for (int c = 0; c < 8; c++) a[c] = fmaxf(a[c], 0.0f);
    float* dst = &xout[(size_t)(b * NN + i) * FF + c8 * 8];
    *(float4*)dst       = make_float4(a[0], a[1], a[2], a[3]);
    *(float4*)(dst + 4) = make_float4(a[4], a[5], a[6], a[7]);
}

// ---------------- K4/K5: concat max-pool + linear --------------------------
__global__ __launch_bounds__(PRED_IN) void pool1() {
    const int chunk = blockIdx.x;
    const int b     = blockIdx.y;
    const int f     = threadIdx.x;
    const float* src; int fo;
    if (f < 128)       { src = g_x1; fo = f; }
    else if (f < 256)  { src = g_x2; fo = f - 128; }
    else               { src = g_x3; fo = f - 256; }
    src += (size_t)b * NN * FF + fo;
    const int n0 = chunk * 128;
    float m = -INFINITY;
#pragma unroll 8
    for (int n = 0; n < 128; n++)
        m = fmaxf(m, src[(size_t)(n0 + n) * FF]);
    g_pmax[(b * 8 + chunk) * PRED_IN + f] = m;
}

__global__ __launch_bounds__(PRED_IN) void pool2(const float* __restrict__ pw,
                                                 const float* __restrict__ pb,
                                                 float* __restrict__ out) {
    __shared__ float pooled[PRED_IN];
    const int b = blockIdx.x;
    const int f = threadIdx.x;
    float m = -INFINITY;
#pragma unroll
    for (int c = 0; c < 8; c++)
        m = fmaxf(m, g_pmax[(b * 8 + c) * PRED_IN + f]);
    pooled[f] = m;
    __syncthreads();
    if (f < LDIM) {
        float acc = pb[f];
        for (int k = 0; k < PRED_IN; k++)
            acc = fmaf(pooled[k], pw[k * LDIM + f], acc);
        out[b * LDIM + f] = acc;
    }
}

// ---------------- launch ----------------------------------------------------
extern "C" void kernel_launch(void* const* d_in, const int* in_sizes, int n_in,
                              void* d_out, int out_size) {
    const float* x   = (const float*)d_in[0];
    const float* adj = (const float*)d_in[1];
    const float* w1  = (const float*)d_in[2];
    const float* as1 = (const float*)d_in[3];
    const float* ad1 = (const float*)d_in[4];
    const float* b1  = (const float*)d_in[5];
    const float* w2  = (const float*)d_in[6];
    const float* as2 = (const float*)d_in[7];
    const float* ad2 = (const float*)d_in[8];
    const float* b2  = (const float*)d_in[9];
    const float* w3  = (const float*)d_in[10];
    const float* as3 = (const float*)d_in[11];
    const float* ad3 = (const float*)d_in[12];
    const float* b3  = (const float*)d_in[13];
    const float* pw  = (const float*)d_in[14];
    const float* pb  = (const float*)d_in[15];
    float* out = (float*)d_out;

    float* x1; cudaGetSymbolAddress((void**)&x1, g_x1);
    float* x2; cudaGetSymbolAddress((void**)&x2, g_x2);
    float* x3; cudaGetSymbolAddress((void**)&x3, g_x3);

    const int gsm  = 512 * FF * sizeof(__half);                 // 128 KB
    const int gemsm = 2 * 128 * ASTRIDE * 2 + 2 * 1024 + 1024;  // 72704 B
    static int smem_set = 0;
    if (!smem_set) {
        cudaFuncSetAttribute(gat_gather,
                             cudaFuncAttributeMaxDynamicSharedMemorySize, gsm);
        cudaFuncSetAttribute(gat_gemm,
                             cudaFuncAttributeMaxDynamicSharedMemorySize, gemsm);
        smem_set = 1;
    }

    build_nbr<<<BB * NN / 8, 256>>>(adj);

    dim3 ggrid(64, HH);
    dim3 grgrid(2, HH, BB);
    const int wgrid = BB * NN * HH / 8;
    const int hrgrid = BB * NN * FF / 8 / 256;

    gat_gemm<<<ggrid, 256, gemsm>>>(x,  w1, as1, ad1);
    attn_weights<<<wgrid, 256>>>();
    gat_gather<<<grgrid, 1024, gsm>>>();
    head_reduce<<<hrgrid, 256>>>(b1, x1, 1);

    gat_gemm<<<ggrid, 256, gemsm>>>(x1, w2, as2, ad2);
    attn_weights<<<wgrid, 256>>>();
    gat_gather<<<grgrid, 1024, gsm>>>();
    head_reduce<<<hrgrid, 256>>>(b2, x2, 1);

    gat_gemm<<<ggrid, 256, gemsm>>>(x2, w3, as3, ad3);
    attn_weights<<<wgrid, 256>>>();
    gat_gather<<<grgrid, 1024, gsm>>>();
    head_reduce<<<hrgrid, 256>>>(b3, x3, 0);

    pool1<<<dim3(8, BB), PRED_IN>>>();
    pool2<<<BB, PRED_IN>>>(pw, pb, out);
}

// round 15
// speedup vs baseline: 1.5547x; 1.5547x over previous
#include <cuda_runtime.h>
#include <cuda_fp16.h>
#include <math.h>

#define BB   8
#define NN   1024
#define FF   128
#define HH   8
#define MAXN 256
#define PRED_IN 384
#define LDIM 2
#define ASTRIDE 136   // fp16 smem row stride

// ---------------- device scratch ----------------
__device__ int    g_nbr[BB * NN * MAXN];
__device__ int    g_cnt[BB * NN];
__device__ int    g_qoff[BB * NN * 4];
__device__ __half g_hp16[(size_t)BB * HH * NN * FF];     // 16 MB
__device__ float  g_s[BB * HH * NN];
__device__ float  g_d[BB * HH * NN];
__device__ uint2  g_ep[(size_t)BB * HH * NN * MAXN];     // 128 MB {off,p}
__device__ __half g_po2h[(size_t)2 * BB * HH * NN * FF]; // 33 MB fp16 partials
__device__ float  g_x1[BB * NN * FF];
__device__ float  g_x2[BB * NN * FF];
__device__ float  g_x3[BB * NN * FF];
__device__ float  g_pmax[BB * 8 * PRED_IN];

__device__ __forceinline__ float tanh_fast(float x) {
    float y;
    asm("tanh.approx.f32 %0, %1;" : "=f"(y) : "f"(x));
    return y;
}

// ---------------- K1: adjacency -> neighbor lists + quartile offsets -------
__global__ __launch_bounds__(256) void build_nbr(const float* __restrict__ adj) {
    int wgl  = blockIdx.x * 8 + (threadIdx.x >> 5);
    int lane = threadIdx.x & 31;
    int b = wgl / NN;
    int i = wgl % NN;
    const float* row = adj + (size_t)(b * NN + i) * NN;
    int base = 0;
    int qof[4];
    for (int c = 0; c < NN; c += 32) {
        float v = row[c + lane];
        unsigned m = __ballot_sync(0xffffffffu, v > 0.0f);
        if (v > 0.0f) {
            int pos = base + __popc(m & ((1u << lane) - 1u));
            if (pos < MAXN) g_nbr[(b * NN + i) * MAXN + pos] = c + lane;
        }
        base += __popc(m);
        if (((c + 32) & 255) == 0)
            qof[((c + 32) >> 8) - 1] = min(base, MAXN);
    }
    if (lane == 0) {
        g_cnt[b * NN + i] = min(base, MAXN);
        *(int4*)&g_qoff[(b * NN + i) * 4] =
            make_int4(qof[0], qof[1], qof[2], qof[3]);
    }
}

// ---------------- K2: fp16 tensor-core GEMM + fused tanh-dot epilogue ------
#define MMA16816(d, a, b) asm volatile( \
    "mma.sync.aligned.m16n8k16.row.col.f32.f16.f16.f32 " \
    "{%0,%1,%2,%3}, {%4,%5,%6,%7}, {%8,%9}, {%0,%1,%2,%3};" \
    : "+f"(d[0]), "+f"(d[1]), "+f"(d[2]), "+f"(d[3]) \
    : "r"(a[0]), "r"(a[1]), "r"(a[2]), "r"(a[3]), "r"(b[0]), "r"(b[1]))

__global__ __launch_bounds__(256) void gat_gemm(const float* __restrict__ x,
                                                const float* __restrict__ w,
                                                const float* __restrict__ asrc,
                                                const float* __restrict__ adst) {
    extern __shared__ __align__(16) char dynsm[];
    __half* A_s  = (__half*)dynsm;                          // [128][136]
    __half* Bt_s = (__half*)(dynsm + 128 * ASTRIDE * 2);    // [128][136]
    float*  redS = (float*)(dynsm + 2 * 128 * ASTRIDE * 2); // [128][2]
    float*  redD = redS + 256;
    float*  sa   = redD + 256;
    float*  da   = sa + 128;

    const int mt  = blockIdx.x;
    const int h   = blockIdx.y;
    const int b   = mt >> 3;
    const int n0m = (mt & 7) * 128;
    const int bh  = b * HH + h;

    const int tid  = threadIdx.x;
    const int warp = tid >> 5;
    const int lane = tid & 31;
    const int wm   = warp & 3;
    const int wn   = warp >> 2;
    const int g    = lane >> 2;
    const int tq   = lane & 3;

    if (tid < FF) { sa[tid] = asrc[h * FF + tid]; da[tid] = adst[h * FF + tid]; }

    const float* xb = x + (size_t)(b * NN + n0m) * FF;
#pragma unroll
    for (int it = 0; it < 16; it++) {
        int idx = tid + it * 256;
        int row = idx >> 5;
        int kq  = (idx & 31) * 4;
        float4 v = *(const float4*)&xb[(size_t)row * FF + kq];
        *(__half2*)&A_s[row * ASTRIDE + kq]     = __floats2half2_rn(v.x, v.y);
        *(__half2*)&A_s[row * ASTRIDE + kq + 2] = __floats2half2_rn(v.z, v.w);
    }
    const float* wh = w + (size_t)h * FF * FF;
#pragma unroll
    for (int it = 0; it < 16; it++) {
        int idx = tid + it * 256;
        int k  = idx >> 5;
        int nq = (idx & 31) * 4;
        float4 v = *(const float4*)&wh[(size_t)k * FF + nq];
        Bt_s[(nq + 0) * ASTRIDE + k] = __float2half_rn(v.x);
        Bt_s[(nq + 1) * ASTRIDE + k] = __float2half_rn(v.y);
        Bt_s[(nq + 2) * ASTRIDE + k] = __float2half_rn(v.z);
        Bt_s[(nq + 3) * ASTRIDE + k] = __float2half_rn(v.w);
    }
    __syncthreads();

    float acc[2][8][4];
#pragma unroll
    for (int m = 0; m < 2; m++)
#pragma unroll
        for (int n = 0; n < 8; n++)
#pragma unroll
            for (int c = 0; c < 4; c++) acc[m][n][c] = 0.0f;

    const int m0w = wm * 32;
    const int n0w = wn * 64;

#pragma unroll
    for (int ks = 0; ks < 8; ks++) {
        const int kc = ks * 16;
        unsigned a[2][4], bf[8][2];
#pragma unroll
        for (int m = 0; m < 2; m++) {
            int r0 = (m0w + m * 16 + g) * ASTRIDE + kc + tq * 2;
            a[m][0] = *(const unsigned*)&A_s[r0];
            a[m][1] = *(const unsigned*)&A_s[r0 + 8 * ASTRIDE];
            a[m][2] = *(const unsigned*)&A_s[r0 + 8];
            a[m][3] = *(const unsigned*)&A_s[r0 + 8 * ASTRIDE + 8];
        }
#pragma unroll
        for (int n = 0; n < 8; n++) {
            int rb = (n0w + n * 8 + g) * ASTRIDE + kc + tq * 2;
            bf[n][0] = *(const unsigned*)&Bt_s[rb];
            bf[n][1] = *(const unsigned*)&Bt_s[rb + 8];
        }
#pragma unroll
        for (int m = 0; m < 2; m++)
#pragma unroll
            for (int n = 0; n < 8; n++)
                MMA16816(acc[m][n], a[m], bf[n]);
    }
    __syncthreads();

    float sp[2][2], dp[2][2];
#pragma unroll
    for (int m = 0; m < 2; m++)
#pragma unroll
        for (int rh = 0; rh < 2; rh++) { sp[m][rh] = 0.0f; dp[m][rh] = 0.0f; }

#pragma unroll
    for (int m = 0; m < 2; m++)
#pragma unroll
        for (int n = 0; n < 8; n++)
#pragma unroll
            for (int c = 0; c < 4; c++) {
                const int rh  = c >> 1;
                const int row = m0w + m * 16 + g + rh * 8;
                const int col = n0w + n * 8 + tq * 2 + (c & 1);
                const float v = acc[m][n][c];
                A_s[row * ASTRIDE + col] = __float2half_rn(v);
                const float t = tanh_fast(v);
                sp[m][rh] = fmaf(t, sa[col], sp[m][rh]);
                dp[m][rh] = fmaf(t, da[col], dp[m][rh]);
            }
#pragma unroll
    for (int m = 0; m < 2; m++)
#pragma unroll
        for (int rh = 0; rh < 2; rh++) {
            float s = sp[m][rh], d = dp[m][rh];
            s += __shfl_xor_sync(0xffffffffu, s, 1);
            s += __shfl_xor_sync(0xffffffffu, s, 2);
            d += __shfl_xor_sync(0xffffffffu, d, 1);
            d += __shfl_xor_sync(0xffffffffu, d, 2);
            if (tq == 0) {
                const int row = m0w + m * 16 + g + rh * 8;
                redS[row * 2 + wn] = s;
                redD[row * 2 + wn] = d;
            }
        }
    __syncthreads();

    __half* hpo = g_hp16 + ((size_t)bh * NN + n0m) * FF;
#pragma unroll
    for (int it = 0; it < 8; it++) {
        int idx = tid + it * 256;
        int row = idx >> 4;
        int seg = (idx & 15) * 8;
        *(uint4*)&hpo[(size_t)row * FF + seg] =
            *(const uint4*)&A_s[row * ASTRIDE + seg];
    }
    if (tid < 128) {
        g_s[bh * NN + n0m + tid] = redS[tid * 2] + redS[tid * 2 + 1];
        g_d[bh * NN + n0m + tid] = redD[tid * 2] + redD[tid * 2 + 1];
    }
}

// ---------------- K3a: normalized attention weights (packed {off,p}) -------
// off = (j & 511) << 8 : byte offset of j's fp16 row inside its 512-row half.
__global__ __launch_bounds__(256) void attn_weights() {
    const int wg   = blockIdx.x * 8 + (threadIdx.x >> 5);
    const int lane = threadIdx.x & 31;
    const int h  = wg & 7;
    const int ri = wg >> 3;
    const int b  = ri >> 10;
    const int i  = ri & 1023;

    const int cnt = g_cnt[b * NN + i];
    const int* nb = &g_nbr[(b * NN + i) * MAXN];
    const float* dd = g_d + (b * HH + h) * NN;
    const float  si = g_s[(b * HH + h) * NN + i];
    uint2* ep = &g_ep[(size_t)((b * HH + h) * NN + i) * MAXN];

    float m = -1e30f;
    float scv[8];
    int   jv[8];
#pragma unroll
    for (int t = 0; t < 8; t++) {
        int k = lane + t * 32;
        float sc = -1e30f;
        int j = 0;
        if (k < cnt) {
            j = nb[k];
            sc = si + dd[j];
            sc = sc >= 0.0f ? sc : 0.2f * sc;
        }
        jv[t] = j;
        scv[t] = sc;
        m = fmaxf(m, sc);
    }
#pragma unroll
    for (int off = 16; off > 0; off >>= 1)
        m = fmaxf(m, __shfl_xor_sync(0xffffffffu, m, off));

    float ssum = 0.0f;
    float ev[8];
#pragma unroll
    for (int t = 0; t < 8; t++) {
        int k = lane + t * 32;
        float e = 0.0f;
        if (k < cnt) e = __expf(scv[t] - m);
        ev[t] = e;
        ssum += e;
    }
#pragma unroll
    for (int off = 16; off > 0; off >>= 1)
        ssum += __shfl_xor_sync(0xffffffffu, ssum, off);
    const float wsc = (1.0f / (float)HH) / ssum;

#pragma unroll
    for (int t = 0; t < 8; t++) {
        int k = lane + t * 32;
        if (k < cnt)
            ep[k] = make_uint2((unsigned)((jv[t] & 511) << 8),
                               __float_as_uint(ev[t] * wsc));
    }
}

// ---------------- K3b: half-owned fp16 smem gather (R12 structure) ---------
__global__ __launch_bounds__(1024) void gat_gather() {
    extern __shared__ __align__(16) char hpb[];   // [512][128] fp16 = 128 KB
    const int q   = blockIdx.x;           // 0..1
    const int h   = blockIdx.y;
    const int b   = blockIdx.z;
    const int tid = threadIdx.x;
    const int w    = tid >> 5;
    const int lane = tid & 31;
    const int group = lane >> 4;
    const int gl    = lane & 15;
    const int bh  = b * HH + h;

    const __half* src = g_hp16 + ((size_t)bh * NN + q * 512) * FF;
#pragma unroll
    for (int it = 0; it < 8; it++) {
        int idx = tid + it * 1024;
        ((uint4*)hpb)[idx] = ((const uint4*)src)[idx];
    }
    __syncthreads();

    __half* po = g_po2h + ((size_t)q * BB * HH + bh) * NN * FF;
    const int gl16 = gl * 16;

#pragma unroll 1
    for (int ii = 0; ii < 16; ii++) {
        const int i = ii * 64 + w * 2 + group;
        const int4 qq = *(const int4*)&g_qoff[(b * NN + i) * 4];
        const int lo = q ? qq.y : 0;
        const int hi = q ? qq.w : qq.y;
        const uint2* ep = &g_ep[(size_t)(bh * NN + i) * MAXN];

        float a0 = 0.f, a1 = 0.f, a2 = 0.f, a3 = 0.f;
        float a4 = 0.f, a5 = 0.f, a6 = 0.f, a7 = 0.f;
        for (int k0 = lo; k0 < hi; k0 += 8) {
            uint2 r[8];
#pragma unroll
            for (int t = 0; t < 8; t++)
                r[t] = (k0 + t < hi) ? __ldg(ep + k0 + t)
                                     : make_uint2(0u, 0u);
#pragma unroll
            for (int t = 0; t < 8; t++) {
                const float p = __uint_as_float(r[t].y);
                uint4 hv = *(const uint4*)(hpb + r[t].x + gl16);
                float2 f0 = __half22float2(*(__half2*)&hv.x);
                float2 f1 = __half22float2(*(__half2*)&hv.y);
                float2 f2 = __half22float2(*(__half2*)&hv.z);
                float2 f3 = __half22float2(*(__half2*)&hv.w);
                a0 = fmaf(p, f0.x, a0); a1 = fmaf(p, f0.y, a1);
                a2 = fmaf(p, f1.x, a2); a3 = fmaf(p, f1.y, a3);
                a4 = fmaf(p, f2.x, a4); a5 = fmaf(p, f2.y, a5);
                a6 = fmaf(p, f3.x, a6); a7 = fmaf(p, f3.y, a7);
            }
        }
        uint4 outv;
        *(__half2*)&outv.x = __floats2half2_rn(a0, a1);
        *(__half2*)&outv.y = __floats2half2_rn(a2, a3);
        *(__half2*)&outv.z = __floats2half2_rn(a4, a5);
        *(__half2*)&outv.w = __floats2half2_rn(a6, a7);
        *(uint4*)&po[(size_t)i * FF + gl * 8] = outv;
    }
}

// ---------------- K3c: reduce 2 halves x 8 heads + bias (+ReLU) ------------
__global__ __launch_bounds__(256) void head_reduce(const float* __restrict__ bias,
                                                   float* __restrict__ xout,
                                                   int do_relu) {
    const int idx = blockIdx.x * 256 + threadIdx.x;
    const int ig  = idx >> 4;
    const int c8  = idx & 15;
    const int b   = ig >> 10;
    const int i   = ig & 1023;

    float a[8];
#pragma unroll
    for (int c = 0; c < 8; c++) a[c] = 0.0f;
#pragma unroll
    for (int qh = 0; qh < 2 * HH; qh++) {
        const int q = qh >> 3;
        const int h = qh & 7;
        const uint4 v = *(const uint4*)
            &g_po2h[(((size_t)q * BB * HH + b * HH + h) * NN + i) * FF + c8 * 8];
        float2 f0 = __half22float2(*(__half2*)&v.x);
        float2 f1 = __half22float2(*(__half2*)&v.y);
        float2 f2 = __half22float2(*(__half2*)&v.z);
        float2 f3 = __half22float2(*(__half2*)&v.w);
        a[0] += f0.x; a[1] += f0.y; a[2] += f1.x; a[3] += f1.y;
        a[4] += f2.x; a[5] += f2.y; a[6] += f3.x; a[7] += f3.y;
    }
    const float4 b0 = *(const float4*)&bias[c8 * 8];
    const float4 b1 = *(const float4*)&bias[c8 * 8 + 4];
    a[0] += b0.x; a[1] += b0.y; a[2] += b0.z; a[3] += b0.w;
    a[4] += b1.x; a[5] += b1.y; a[6] += b1.z; a[7] += b1.w;
    if (do_relu)
#pragma unroll
        for (int c = 0; c < 8; c++) a[c] = fmaxf(a[c], 0.0f);
    float* dst = &xout[(size_t)(b * NN + i) * FF + c8 * 8];
    *(float4*)dst       = make_float4(a[0], a[1], a[2], a[3]);
    *(float4*)(dst + 4) = make_float4(a[4], a[5], a[6], a[7]);
}

// ---------------- K4/K5: concat max-pool + linear --------------------------
__global__ __launch_bounds__(PRED_IN) void pool1() {
    const int chunk = blockIdx.x;
    const int b     = blockIdx.y;
    const int f     = threadIdx.x;
    const float* src; int fo;
    if (f < 128)       { src = g_x1; fo = f; }
    else if (f < 256)  { src = g_x2; fo = f - 128; }
    else               { src = g_x3; fo = f - 256; }
    src += (size_t)b * NN * FF + fo;
    const int n0 = chunk * 128;
    float m = -INFINITY;
#pragma unroll 8
    for (int n = 0; n < 128; n++)
        m = fmaxf(m, src[(size_t)(n0 + n) * FF]);
    g_pmax[(b * 8 + chunk) * PRED_IN + f] = m;
}

__global__ __launch_bounds__(PRED_IN) void pool2(const float* __restrict__ pw,
                                                 const float* __restrict__ pb,
                                                 float* __restrict__ out) {
    __shared__ float pooled[PRED_IN];
    const int b = blockIdx.x;
    const int f = threadIdx.x;
    float m = -INFINITY;
#pragma unroll
    for (int c = 0; c < 8; c++)
        m = fmaxf(m, g_pmax[(b * 8 + c) * PRED_IN + f]);
    pooled[f] = m;
    __syncthreads();
    if (f < LDIM) {
        float acc = pb[f];
        for (int k = 0; k < PRED_IN; k++)
            acc = fmaf(pooled[k], pw[k * LDIM + f], acc);
        out[b * LDIM + f] = acc;
    }
}

// ---------------- launch ----------------------------------------------------
extern "C" void kernel_launch(void* const* d_in, const int* in_sizes, int n_in,
                              void* d_out, int out_size) {
    const float* x   = (const float*)d_in[0];
    const float* adj = (const float*)d_in[1];
    const float* w1  = (const float*)d_in[2];
    const float* as1 = (const float*)d_in[3];
    const float* ad1 = (const float*)d_in[4];
    const float* b1  = (const float*)d_in[5];
    const float* w2  = (const float*)d_in[6];
    const float* as2 = (const float*)d_in[7];
    const float* ad2 = (const float*)d_in[8];
    const float* b2  = (const float*)d_in[9];
    const float* w3  = (const float*)d_in[10];
    const float* as3 = (const float*)d_in[11];
    const float* ad3 = (const float*)d_in[12];
    const float* b3  = (const float*)d_in[13];
    const float* pw  = (const float*)d_in[14];
    const float* pb  = (const float*)d_in[15];
    float* out = (float*)d_out;

    float* x1; cudaGetSymbolAddress((void**)&x1, g_x1);
    float* x2; cudaGetSymbolAddress((void**)&x2, g_x2);
    float* x3; cudaGetSymbolAddress((void**)&x3, g_x3);

    const int gsm  = 512 * FF * sizeof(__half);                 // 128 KB
    const int gemsm = 2 * 128 * ASTRIDE * 2 + 2 * 1024 + 1024;  // 72704 B
    static int smem_set = 0;
    if (!smem_set) {
        cudaFuncSetAttribute(gat_gather,
                             cudaFuncAttributeMaxDynamicSharedMemorySize, gsm);
        cudaFuncSetAttribute(gat_gemm,
                             cudaFuncAttributeMaxDynamicSharedMemorySize, gemsm);
        smem_set = 1;
    }

    build_nbr<<<BB * NN / 8, 256>>>(adj);

    dim3 ggrid(64, HH);
    dim3 grgrid(2, HH, BB);
    const int wgrid = BB * NN * HH / 8;
    const int hrgrid = BB * NN * FF / 8 / 256;

    gat_gemm<<<ggrid, 256, gemsm>>>(x,  w1, as1, ad1);
    attn_weights<<<wgrid, 256>>>();
    gat_gather<<<grgrid, 1024, gsm>>>();
    head_reduce<<<hrgrid, 256>>>(b1, x1, 1);

    gat_gemm<<<ggrid, 256, gemsm>>>(x1, w2, as2, ad2);
    attn_weights<<<wgrid, 256>>>();
    gat_gather<<<grgrid, 1024, gsm>>>();
    head_reduce<<<hrgrid, 256>>>(b2, x2, 1);

    gat_gemm<<<ggrid, 256, gemsm>>>(x2, w3, as3, ad3);
    attn_weights<<<wgrid, 256>>>();
    gat_gather<<<grgrid, 1024, gsm>>>();
    head_reduce<<<hrgrid, 256>>>(b3, x3, 0);

    pool1<<<dim3(8, BB), PRED_IN>>>();
    pool2<<<BB, PRED_IN>>>(pw, pb, out);
}

// round 16
// speedup vs baseline: 1.7636x; 1.1344x over previous
#include <cuda_runtime.h>
#include <cuda_fp16.h>
#include <math.h>

#define BB   8
#define NN   1024
#define FF   128
#define HH   8
#define MAXN 256
#define PRED_IN 384
#define LDIM 2
#define ASTRIDE 136   // fp16 smem row stride (272 B rows, 16B-aligned)

// ---------------- device scratch ----------------
__device__ int    g_nbr[BB * NN * MAXN];
__device__ int    g_cnt[BB * NN];
__device__ int    g_qoff[BB * NN * 4];
__device__ __half g_hp16[(size_t)BB * HH * NN * FF];     // 16 MB
__device__ float  g_s[BB * HH * NN];
__device__ float  g_d[BB * HH * NN];
__device__ uint2  g_ep[(size_t)BB * HH * NN * MAXN];     // {off,p}
__device__ __half g_po2h[(size_t)2 * BB * HH * NN * FF]; // fp16 partials
__device__ float  g_x1[BB * NN * FF];
__device__ float  g_x2[BB * NN * FF];
__device__ float  g_x3[BB * NN * FF];
__device__ float  g_pmax[BB * 8 * PRED_IN];

__device__ __forceinline__ float tanh_fast(float x) {
    float y;
    asm("tanh.approx.f32 %0, %1;" : "=f"(y) : "f"(x));
    return y;
}

// ---------------- K1: adjacency -> neighbor lists + quartile offsets -------
__global__ __launch_bounds__(256) void build_nbr(const float* __restrict__ adj) {
    int wgl  = blockIdx.x * 8 + (threadIdx.x >> 5);
    int lane = threadIdx.x & 31;
    int b = wgl / NN;
    int i = wgl % NN;
    const float* row = adj + (size_t)(b * NN + i) * NN;
    int base = 0;
    int qof[4];
    for (int c = 0; c < NN; c += 32) {
        float v = row[c + lane];
        unsigned m = __ballot_sync(0xffffffffu, v > 0.0f);
        if (v > 0.0f) {
            int pos = base + __popc(m & ((1u << lane) - 1u));
            if (pos < MAXN) g_nbr[(b * NN + i) * MAXN + pos] = c + lane;
        }
        base += __popc(m);
        if (((c + 32) & 255) == 0)
            qof[((c + 32) >> 8) - 1] = min(base, MAXN);
    }
    if (lane == 0) {
        g_cnt[b * NN + i] = min(base, MAXN);
        *(int4*)&g_qoff[(b * NN + i) * 4] =
            make_int4(qof[0], qof[1], qof[2], qof[3]);
    }
}

// ---------------- K2: fp16 tensor-core GEMM (ldmatrix) + fused epilogue ----
#define MMA16816(d, a, b) asm volatile( \
    "mma.sync.aligned.m16n8k16.row.col.f32.f16.f16.f32 " \
    "{%0,%1,%2,%3}, {%4,%5,%6,%7}, {%8,%9}, {%0,%1,%2,%3};" \
    : "+f"(d[0]), "+f"(d[1]), "+f"(d[2]), "+f"(d[3]) \
    : "r"(a[0]), "r"(a[1]), "r"(a[2]), "r"(a[3]), "r"(b[0]), "r"(b[1]))

#define LDSM_X4(r0, r1, r2, r3, addr) asm volatile( \
    "ldmatrix.sync.aligned.m8n8.x4.shared.b16 {%0,%1,%2,%3}, [%4];" \
    : "=r"(r0), "=r"(r1), "=r"(r2), "=r"(r3) : "r"(addr))

#define LDSM_X4_T(r0, r1, r2, r3, addr) asm volatile( \
    "ldmatrix.sync.aligned.m8n8.x4.trans.shared.b16 {%0,%1,%2,%3}, [%4];" \
    : "=r"(r0), "=r"(r1), "=r"(r2), "=r"(r3) : "r"(addr))

__global__ __launch_bounds__(256) void gat_gemm(const float* __restrict__ x,
                                                const float* __restrict__ w,
                                                const float* __restrict__ asrc,
                                                const float* __restrict__ adst) {
    extern __shared__ __align__(16) char dynsm[];
    __half* A_s = (__half*)dynsm;                          // [128][136]
    __half* B_s = (__half*)(dynsm + 128 * ASTRIDE * 2);    // [128][136] k-major
    float*  redS = (float*)(dynsm + 2 * 128 * ASTRIDE * 2);
    float*  redD = redS + 256;
    float*  sa   = redD + 256;
    float*  da   = sa + 128;

    const int mt  = blockIdx.x;
    const int h   = blockIdx.y;
    const int b   = mt >> 3;
    const int n0m = (mt & 7) * 128;
    const int bh  = b * HH + h;

    const int tid  = threadIdx.x;
    const int warp = tid >> 5;
    const int lane = tid & 31;
    const int wm   = warp & 3;
    const int wn   = warp >> 2;
    const int g    = lane >> 2;
    const int tq   = lane & 3;

    if (tid < FF) { sa[tid] = asrc[h * FF + tid]; da[tid] = adst[h * FF + tid]; }

    // stage A = x tile (fp32 -> fp16), row-major, conflict-free
    const float* xb = x + (size_t)(b * NN + n0m) * FF;
#pragma unroll
    for (int it = 0; it < 16; it++) {
        int idx = tid + it * 256;
        int row = idx >> 5;
        int kq  = (idx & 31) * 4;
        float4 v = *(const float4*)&xb[(size_t)row * FF + kq];
        *(__half2*)&A_s[row * ASTRIDE + kq]     = __floats2half2_rn(v.x, v.y);
        *(__half2*)&A_s[row * ASTRIDE + kq + 2] = __floats2half2_rn(v.z, v.w);
    }
    // stage B = w[h] K-MAJOR (same pattern as A; no transpose, no conflicts)
    const float* wh = w + (size_t)h * FF * FF;
#pragma unroll
    for (int it = 0; it < 16; it++) {
        int idx = tid + it * 256;
        int k  = idx >> 5;
        int nq = (idx & 31) * 4;
        float4 v = *(const float4*)&wh[(size_t)k * FF + nq];
        *(__half2*)&B_s[k * ASTRIDE + nq]     = __floats2half2_rn(v.x, v.y);
        *(__half2*)&B_s[k * ASTRIDE + nq + 2] = __floats2half2_rn(v.z, v.w);
    }
    __syncthreads();

    float acc[2][8][4];
#pragma unroll
    for (int m = 0; m < 2; m++)
#pragma unroll
        for (int n = 0; n < 8; n++)
#pragma unroll
            for (int c = 0; c < 4; c++) acc[m][n][c] = 0.0f;

    const int m0w = wm * 32;
    const int n0w = wn * 64;

    // ldmatrix lane address components (same pattern for A and B):
    //   row/k index: base + (lane & 15); col: base + (lane >> 4) * 8
    const int l15 = lane & 15;
    const int l16 = (lane >> 4) * 8;
    const unsigned aBase = (unsigned)__cvta_generic_to_shared(A_s);
    const unsigned bBase = (unsigned)__cvta_generic_to_shared(B_s);

#pragma unroll
    for (int ks = 0; ks < 8; ks++) {
        const int kc = ks * 16;
        unsigned a[2][4], bf[8][2];
        // A fragments: 16x16 tile per m via ldmatrix.x4
#pragma unroll
        for (int m = 0; m < 2; m++) {
            unsigned addr = aBase +
                ((m0w + m * 16 + l15) * ASTRIDE + kc + l16) * 2;
            LDSM_X4(a[m][0], a[m][1], a[m][2], a[m][3], addr);
        }
        // B fragments: two 8-wide n-tiles per ldmatrix.x4.trans (k-major src)
#pragma unroll
        for (int np = 0; np < 4; np++) {
            unsigned addr = bBase +
                ((kc + l15) * ASTRIDE + n0w + np * 16 + l16) * 2;
            LDSM_X4_T(bf[np * 2][0], bf[np * 2][1],
                      bf[np * 2 + 1][0], bf[np * 2 + 1][1], addr);
        }
#pragma unroll
        for (int m = 0; m < 2; m++)
#pragma unroll
            for (int n = 0; n < 8; n++)
                MMA16816(acc[m][n], a[m], bf[n]);
    }
    __syncthreads();

    float sp[2][2], dp[2][2];
#pragma unroll
    for (int m = 0; m < 2; m++)
#pragma unroll
        for (int rh = 0; rh < 2; rh++) { sp[m][rh] = 0.0f; dp[m][rh] = 0.0f; }

#pragma unroll
    for (int m = 0; m < 2; m++)
#pragma unroll
        for (int n = 0; n < 8; n++)
#pragma unroll
            for (int c = 0; c < 4; c++) {
                const int rh  = c >> 1;
                const int row = m0w + m * 16 + g + rh * 8;
                const int col = n0w + n * 8 + tq * 2 + (c & 1);
                const float v = acc[m][n][c];
                A_s[row * ASTRIDE + col] = __float2half_rn(v);
                const float t = tanh_fast(v);
                sp[m][rh] = fmaf(t, sa[col], sp[m][rh]);
                dp[m][rh] = fmaf(t, da[col], dp[m][rh]);
            }
#pragma unroll
    for (int m = 0; m < 2; m++)
#pragma unroll
        for (int rh = 0; rh < 2; rh++) {
            float s = sp[m][rh], d = dp[m][rh];
            s += __shfl_xor_sync(0xffffffffu, s, 1);
            s += __shfl_xor_sync(0xffffffffu, s, 2);
            d += __shfl_xor_sync(0xffffffffu, d, 1);
            d += __shfl_xor_sync(0xffffffffu, d, 2);
            if (tq == 0) {
                const int row = m0w + m * 16 + g + rh * 8;
                redS[row * 2 + wn] = s;
                redD[row * 2 + wn] = d;
            }
        }
    __syncthreads();

    __half* hpo = g_hp16 + ((size_t)bh * NN + n0m) * FF;
#pragma unroll
    for (int it = 0; it < 8; it++) {
        int idx = tid + it * 256;
        int row = idx >> 4;
        int seg = (idx & 15) * 8;
        *(uint4*)&hpo[(size_t)row * FF + seg] =
            *(const uint4*)&A_s[row * ASTRIDE + seg];
    }
    if (tid < 128) {
        g_s[bh * NN + n0m + tid] = redS[tid * 2] + redS[tid * 2 + 1];
        g_d[bh * NN + n0m + tid] = redD[tid * 2] + redD[tid * 2 + 1];
    }
}

// ---------------- K3a: normalized attention weights (packed {off,p}) -------
__global__ __launch_bounds__(256) void attn_weights() {
    const int wg   = blockIdx.x * 8 + (threadIdx.x >> 5);
    const int lane = threadIdx.x & 31;
    const int h  = wg & 7;
    const int ri = wg >> 3;
    const int b  = ri >> 10;
    const int i  = ri & 1023;

    const int cnt = g_cnt[b * NN + i];
    const int* nb = &g_nbr[(b * NN + i) * MAXN];
    const float* dd = g_d + (b * HH + h) * NN;
    const float  si = g_s[(b * HH + h) * NN + i];
    uint2* ep = &g_ep[(size_t)((b * HH + h) * NN + i) * MAXN];

    float m = -1e30f;
    float scv[8];
    int   jv[8];
#pragma unroll
    for (int t = 0; t < 8; t++) {
        int k = lane + t * 32;
        float sc = -1e30f;
        int j = 0;
        if (k < cnt) {
            j = nb[k];
            sc = si + dd[j];
            sc = sc >= 0.0f ? sc : 0.2f * sc;
        }
        jv[t] = j;
        scv[t] = sc;
        m = fmaxf(m, sc);
    }
#pragma unroll
    for (int off = 16; off > 0; off >>= 1)
        m = fmaxf(m, __shfl_xor_sync(0xffffffffu, m, off));

    float ssum = 0.0f;
    float ev[8];
#pragma unroll
    for (int t = 0; t < 8; t++) {
        int k = lane + t * 32;
        float e = 0.0f;
        if (k < cnt) e = __expf(scv[t] - m);
        ev[t] = e;
        ssum += e;
    }
#pragma unroll
    for (int off = 16; off > 0; off >>= 1)
        ssum += __shfl_xor_sync(0xffffffffu, ssum, off);
    const float wsc = (1.0f / (float)HH) / ssum;

#pragma unroll
    for (int t = 0; t < 8; t++) {
        int k = lane + t * 32;
        if (k < cnt)
            ep[k] = make_uint2((unsigned)((jv[t] & 511) << 8),
                               __float_as_uint(ev[t] * wsc));
    }
}

// ---------------- K3b: half-owned fp16 smem gather (R12 structure) ---------
__global__ __launch_bounds__(1024) void gat_gather() {
    extern __shared__ __align__(16) char hpb[];   // [512][128] fp16 = 128 KB
    const int q   = blockIdx.x;           // 0..1
    const int h   = blockIdx.y;
    const int b   = blockIdx.z;
    const int tid = threadIdx.x;
    const int w    = tid >> 5;
    const int lane = tid & 31;
    const int group = lane >> 4;
    const int gl    = lane & 15;
    const int bh  = b * HH + h;

    const __half* src = g_hp16 + ((size_t)bh * NN + q * 512) * FF;
#pragma unroll
    for (int it = 0; it < 8; it++) {
        int idx = tid + it * 1024;
        ((uint4*)hpb)[idx] = ((const uint4*)src)[idx];
    }
    __syncthreads();

    __half* po = g_po2h + ((size_t)q * BB * HH + bh) * NN * FF;
    const int gl16 = gl * 16;

#pragma unroll 1
    for (int ii = 0; ii < 16; ii++) {
        const int i = ii * 64 + w * 2 + group;
        const int4 qq = *(const int4*)&g_qoff[(b * NN + i) * 4];
        const int lo = q ? qq.y : 0;
        const int hi = q ? qq.w : qq.y;
        const uint2* ep = &g_ep[(size_t)(bh * NN + i) * MAXN];

        float a0 = 0.f, a1 = 0.f, a2 = 0.f, a3 = 0.f;
        float a4 = 0.f, a5 = 0.f, a6 = 0.f, a7 = 0.f;
        for (int k0 = lo; k0 < hi; k0 += 8) {
            uint2 r[8];
#pragma unroll
            for (int t = 0; t < 8; t++)
                r[t] = (k0 + t < hi) ? __ldg(ep + k0 + t)
                                     : make_uint2(0u, 0u);
#pragma unroll
            for (int t = 0; t < 8; t++) {
                const float p = __uint_as_float(r[t].y);
                uint4 hv = *(const uint4*)(hpb + r[t].x + gl16);
                float2 f0 = __half22float2(*(__half2*)&hv.x);
                float2 f1 = __half22float2(*(__half2*)&hv.y);
                float2 f2 = __half22float2(*(__half2*)&hv.z);
                float2 f3 = __half22float2(*(__half2*)&hv.w);
                a0 = fmaf(p, f0.x, a0); a1 = fmaf(p, f0.y, a1);
                a2 = fmaf(p, f1.x, a2); a3 = fmaf(p, f1.y, a3);
                a4 = fmaf(p, f2.x, a4); a5 = fmaf(p, f2.y, a5);
                a6 = fmaf(p, f3.x, a6); a7 = fmaf(p, f3.y, a7);
            }
        }
        uint4 outv;
        *(__half2*)&outv.x = __floats2half2_rn(a0, a1);
        *(__half2*)&outv.y = __floats2half2_rn(a2, a3);
        *(__half2*)&outv.z = __floats2half2_rn(a4, a5);
        *(__half2*)&outv.w = __floats2half2_rn(a6, a7);
        *(uint4*)&po[(size_t)i * FF + gl * 8] = outv;
    }
}

// ---------------- K3c: reduce 2 halves x 8 heads + bias (+ReLU) ------------
__global__ __launch_bounds__(256) void head_reduce(const float* __restrict__ bias,
                                                   float* __restrict__ xout,
                                                   int do_relu) {
    const int idx = blockIdx.x * 256 + threadIdx.x;
    const int ig  = idx >> 4;
    const int c8  = idx & 15;
    const int b   = ig >> 10;
    const int i   = ig & 1023;

    float a[8];
#pragma unroll
    for (int c = 0; c < 8; c++) a[c] = 0.0f;
#pragma unroll
    for (int qh = 0; qh < 2 * HH; qh++) {
        const int q = qh >> 3;
        const int h = qh & 7;
        const uint4 v = *(const uint4*)
            &g_po2h[(((size_t)q * BB * HH + b * HH + h) * NN + i) * FF + c8 * 8];
        float2 f0 = __half22float2(*(__half2*)&v.x);
        float2 f1 = __half22float2(*(__half2*)&v.y);
        float2 f2 = __half22float2(*(__half2*)&v.z);
        float2 f3 = __half22float2(*(__half2*)&v.w);
        a[0] += f0.x; a[1] += f0.y; a[2] += f1.x; a[3] += f1.y;
        a[4] += f2.x; a[5] += f2.y; a[6] += f3.x; a[7] += f3.y;
    }
    const float4 b0 = *(const float4*)&bias[c8 * 8];
    const float4 b1 = *(const float4*)&bias[c8 * 8 + 4];
    a[0] += b0.x; a[1] += b0.y; a[2] += b0.z; a[3] += b0.w;
    a[4] += b1.x; a[5] += b1.y; a[6] += b1.z; a[7] += b1.w;
    if (do_relu)
#pragma unroll
        for (int c = 0; c < 8; c++) a[c] = fmaxf(a[c], 0.0f);
    float* dst = &xout[(size_t)(b * NN + i) * FF + c8 * 8];
    *(float4*)dst       = make_float4(a[0], a[1], a[2], a[3]);
    *(float4*)(dst + 4) = make_float4(a[4], a[5], a[6], a[7]);
}

// ---------------- K4/K5: concat max-pool + linear --------------------------
__global__ __launch_bounds__(PRED_IN) void pool1() {
    const int chunk = blockIdx.x;
    const int b     = blockIdx.y;
    const int f     = threadIdx.x;
    const float* src; int fo;
    if (f < 128)       { src = g_x1; fo = f; }
    else if (f < 256)  { src = g_x2; fo = f - 128; }
    else               { src = g_x3; fo = f - 256; }
    src += (size_t)b * NN * FF + fo;
    const int n0 = chunk * 128;
    float m = -INFINITY;
#pragma unroll 8
    for (int n = 0; n < 128; n++)
        m = fmaxf(m, src[(size_t)(n0 + n) * FF]);
    g_pmax[(b * 8 + chunk) * PRED_IN + f] = m;
}

__global__ __launch_bounds__(PRED_IN) void pool2(const float* __restrict__ pw,
                                                 const float* __restrict__ pb,
                                                 float* __restrict__ out) {
    __shared__ float pooled[PRED_IN];
    const int b = blockIdx.x;
    const int f = threadIdx.x;
    float m = -INFINITY;
#pragma unroll
    for (int c = 0; c < 8; c++)
        m = fmaxf(m, g_pmax[(b * 8 + c) * PRED_IN + f]);
    pooled[f] = m;
    __syncthreads();
    if (f < LDIM) {
        float acc = pb[f];
        for (int k = 0; k < PRED_IN; k++)
            acc = fmaf(pooled[k], pw[k * LDIM + f], acc);
        out[b * LDIM + f] = acc;
    }
}

// ---------------- launch ----------------------------------------------------
extern "C" void kernel_launch(void* const* d_in, const int* in_sizes, int n_in,
                              void* d_out, int out_size) {
    const float* x   = (const float*)d_in[0];
    const float* adj = (const float*)d_in[1];
    const float* w1  = (const float*)d_in[2];
    const float* as1 = (const float*)d_in[3];
    const float* ad1 = (const float*)d_in[4];
    const float* b1  = (const float*)d_in[5];
    const float* w2  = (const float*)d_in[6];
    const float* as2 = (const float*)d_in[7];
    const float* ad2 = (const float*)d_in[8];
    const float* b2  = (const float*)d_in[9];
    const float* w3  = (const float*)d_in[10];
    const float* as3 = (const float*)d_in[11];
    const float* ad3 = (const float*)d_in[12];
    const float* b3  = (const float*)d_in[13];
    const float* pw  = (const float*)d_in[14];
    const float* pb  = (const float*)d_in[15];
    float* out = (float*)d_out;

    float* x1; cudaGetSymbolAddress((void**)&x1, g_x1);
    float* x2; cudaGetSymbolAddress((void**)&x2, g_x2);
    float* x3; cudaGetSymbolAddress((void**)&x3, g_x3);

    const int gsm  = 512 * FF * sizeof(__half);                 // 128 KB
    const int gemsm = 2 * 128 * ASTRIDE * 2 + 2 * 1024 + 1024;  // 72704 B
    static int smem_set = 0;
    if (!smem_set) {
        cudaFuncSetAttribute(gat_gather,
                             cudaFuncAttributeMaxDynamicSharedMemorySize, gsm);
        cudaFuncSetAttribute(gat_gemm,
                             cudaFuncAttributeMaxDynamicSharedMemorySize, gemsm);
        smem_set = 1;
    }

    build_nbr<<<BB * NN / 8, 256>>>(adj);

    dim3 ggrid(64, HH);
    dim3 grgrid(2, HH, BB);
    const int wgrid = BB * NN * HH / 8;
    const int hrgrid = BB * NN * FF / 8 / 256;

    gat_gemm<<<ggrid, 256, gemsm>>>(x,  w1, as1, ad1);
    attn_weights<<<wgrid, 256>>>();
    gat_gather<<<grgrid, 1024, gsm>>>();
    head_reduce<<<hrgrid, 256>>>(b1, x1, 1);

    gat_gemm<<<ggrid, 256, gemsm>>>(x1, w2, as2, ad2);
    attn_weights<<<wgrid, 256>>>();
    gat_gather<<<grgrid, 1024, gsm>>>();
    head_reduce<<<hrgrid, 256>>>(b2, x2, 1);

    gat_gemm<<<ggrid, 256, gemsm>>>(x2, w3, as3, ad3);
    attn_weights<<<wgrid, 256>>>();
    gat_gather<<<grgrid, 1024, gsm>>>();
    head_reduce<<<hrgrid, 256>>>(b3, x3, 0);

    pool1<<<dim3(8, BB), PRED_IN>>>();
    pool2<<<BB, PRED_IN>>>(pw, pb, out);
}

// round 17
// speedup vs baseline: 1.7900x; 1.0150x over previous
#include <cuda_runtime.h>
#include <cuda_fp16.h>
#include <math.h>

#define BB   8
#define NN   1024
#define FF   128
#define HH   8
#define MAXN 256
#define PRED_IN 384
#define LDIM 2
#define ASTRIDE 136   // fp16 smem row stride (272 B rows, 16B-aligned)

// ---------------- device scratch ----------------
__device__ int    g_nbr[BB * NN * MAXN];
__device__ int    g_cnt[BB * NN];
__device__ int    g_qoff[BB * NN * 4];
__device__ __half g_hp16[(size_t)BB * HH * NN * FF];     // 16 MB
__device__ float  g_s[BB * HH * NN];
__device__ float  g_d[BB * HH * NN];
__device__ uint2  g_ep[(size_t)BB * HH * NN * MAXN];     // {off, p half2}
__device__ __half g_po2h[(size_t)2 * BB * HH * NN * FF]; // fp16 partials
__device__ __half g_xh[BB * NN * FF];                    // fp16 activations
__device__ __half g_wh[3 * HH * FF * FF];                // fp16 weights
__device__ float  g_x1[BB * NN * FF];
__device__ float  g_x2[BB * NN * FF];
__device__ float  g_x3[BB * NN * FF];
__device__ float  g_pmax[BB * 8 * PRED_IN];

__device__ __forceinline__ float tanh_fast(float x) {
    float y;
    asm("tanh.approx.f32 %0, %1;" : "=f"(y) : "f"(x));
    return y;
}

// ---------------- K0: fp32 -> fp16 conversion ------------------------------
__global__ __launch_bounds__(256) void conv_fp16(const float* __restrict__ src,
                                                 __half* __restrict__ dst) {
    const int idx = blockIdx.x * 256 + threadIdx.x;
    float4 v = *(const float4*)&src[(size_t)idx * 4];
    *(__half2*)&dst[(size_t)idx * 4]     = __floats2half2_rn(v.x, v.y);
    *(__half2*)&dst[(size_t)idx * 4 + 2] = __floats2half2_rn(v.z, v.w);
}

// ---------------- K1: adjacency -> neighbor lists + quartile offsets -------
// float4 loads, 4 ballots per 128-chunk, software prefetch. Within-chunk
// edge order is permuted (harmless: boundaries are chunk-aligned).
__global__ __launch_bounds__(256) void build_nbr(const float* __restrict__ adj) {
    int wgl  = blockIdx.x * 8 + (threadIdx.x >> 5);
    int lane = threadIdx.x & 31;
    int b = wgl / NN;
    int i = wgl % NN;
    const float4* row = (const float4*)(adj + (size_t)(b * NN + i) * NN);
    int* nb = &g_nbr[(b * NN + i) * MAXN];
    int base = 0;
    int qof[4];
    float4 v = row[lane];
#pragma unroll
    for (int it = 0; it < 8; it++) {
        float4 vn = make_float4(0.f, 0.f, 0.f, 0.f);
        if (it < 7) vn = row[(it + 1) * 32 + lane];
        const int c = it * 128 + lane * 4;
#pragma unroll
        for (int e = 0; e < 4; e++) {
            float ve = (e == 0) ? v.x : (e == 1) ? v.y : (e == 2) ? v.z : v.w;
            unsigned m = __ballot_sync(0xffffffffu, ve > 0.0f);
            if (ve > 0.0f) {
                int pos = base + __popc(m & ((1u << lane) - 1u));
                if (pos < MAXN) nb[pos] = c + e;
            }
            base += __popc(m);
        }
        if (it & 1) qof[it >> 1] = min(base, MAXN);
        v = vn;
    }
    if (lane == 0) {
        g_cnt[b * NN + i] = min(base, MAXN);
        *(int4*)&g_qoff[(b * NN + i) * 4] =
            make_int4(qof[0], qof[1], qof[2], qof[3]);
    }
}

// ---------------- K2: fp16 tensor-core GEMM (ldmatrix) + fused epilogue ----
#define MMA16816(d, a, b) asm volatile( \
    "mma.sync.aligned.m16n8k16.row.col.f32.f16.f16.f32 " \
    "{%0,%1,%2,%3}, {%4,%5,%6,%7}, {%8,%9}, {%0,%1,%2,%3};" \
    : "+f"(d[0]), "+f"(d[1]), "+f"(d[2]), "+f"(d[3]) \
    : "r"(a[0]), "r"(a[1]), "r"(a[2]), "r"(a[3]), "r"(b[0]), "r"(b[1]))

#define LDSM_X4(r0, r1, r2, r3, addr) asm volatile( \
    "ldmatrix.sync.aligned.m8n8.x4.shared.b16 {%0,%1,%2,%3}, [%4];" \
    : "=r"(r0), "=r"(r1), "=r"(r2), "=r"(r3) : "r"(addr))

#define LDSM_X4_T(r0, r1, r2, r3, addr) asm volatile( \
    "ldmatrix.sync.aligned.m8n8.x4.trans.shared.b16 {%0,%1,%2,%3}, [%4];" \
    : "=r"(r0), "=r"(r1), "=r"(r2), "=r"(r3) : "r"(addr))

__global__ __launch_bounds__(256) void gat_gemm(const __half* __restrict__ wh_all,
                                                const float* __restrict__ asrc,
                                                const float* __restrict__ adst) {
    extern __shared__ __align__(16) char dynsm[];
    __half* A_s = (__half*)dynsm;                          // [128][136]
    __half* B_s = (__half*)(dynsm + 128 * ASTRIDE * 2);    // [128][136] k-major
    float*  redS = (float*)(dynsm + 2 * 128 * ASTRIDE * 2);
    float*  redD = redS + 256;
    float*  sa   = redD + 256;
    float*  da   = sa + 128;

    const int mt  = blockIdx.x;
    const int h   = blockIdx.y;
    const int b   = mt >> 3;
    const int n0m = (mt & 7) * 128;
    const int bh  = b * HH + h;

    const int tid  = threadIdx.x;
    const int warp = tid >> 5;
    const int lane = tid & 31;
    const int wm   = warp & 3;
    const int wn   = warp >> 2;
    const int g    = lane >> 2;
    const int tq   = lane & 3;

    if (tid < FF) { sa[tid] = asrc[h * FF + tid]; da[tid] = adst[h * FF + tid]; }

    // stage A = fp16 activation tile (uint4 copies)
    const __half* xb = g_xh + (size_t)(b * NN + n0m) * FF;
#pragma unroll
    for (int it = 0; it < 8; it++) {
        int idx = tid + it * 256;
        int row = idx >> 4;
        int seg = (idx & 15) * 8;
        *(uint4*)&A_s[row * ASTRIDE + seg] =
            *(const uint4*)&xb[(size_t)row * FF + seg];
    }
    // stage B = fp16 w[h], k-major (uint4 copies)
    const __half* wh = wh_all + (size_t)h * FF * FF;
#pragma unroll
    for (int it = 0; it < 8; it++) {
        int idx = tid + it * 256;
        int k   = idx >> 4;
        int seg = (idx & 15) * 8;
        *(uint4*)&B_s[k * ASTRIDE + seg] =
            *(const uint4*)&wh[(size_t)k * FF + seg];
    }
    __syncthreads();

    float acc[2][8][4];
#pragma unroll
    for (int m = 0; m < 2; m++)
#pragma unroll
        for (int n = 0; n < 8; n++)
#pragma unroll
            for (int c = 0; c < 4; c++) acc[m][n][c] = 0.0f;

    const int m0w = wm * 32;
    const int n0w = wn * 64;
    const int l15 = lane & 15;
    const int l16 = (lane >> 4) * 8;
    const unsigned aBase = (unsigned)__cvta_generic_to_shared(A_s);
    const unsigned bBase = (unsigned)__cvta_generic_to_shared(B_s);

#pragma unroll
    for (int ks = 0; ks < 8; ks++) {
        const int kc = ks * 16;
        unsigned a[2][4], bf[8][2];
#pragma unroll
        for (int m = 0; m < 2; m++) {
            unsigned addr = aBase +
                ((m0w + m * 16 + l15) * ASTRIDE + kc + l16) * 2;
            LDSM_X4(a[m][0], a[m][1], a[m][2], a[m][3], addr);
        }
#pragma unroll
        for (int np = 0; np < 4; np++) {
            unsigned addr = bBase +
                ((kc + l15) * ASTRIDE + n0w + np * 16 + l16) * 2;
            LDSM_X4_T(bf[np * 2][0], bf[np * 2][1],
                      bf[np * 2 + 1][0], bf[np * 2 + 1][1], addr);
        }
#pragma unroll
        for (int m = 0; m < 2; m++)
#pragma unroll
            for (int n = 0; n < 8; n++)
                MMA16816(acc[m][n], a[m], bf[n]);
    }
    __syncthreads();

    float sp[2][2], dp[2][2];
#pragma unroll
    for (int m = 0; m < 2; m++)
#pragma unroll
        for (int rh = 0; rh < 2; rh++) { sp[m][rh] = 0.0f; dp[m][rh] = 0.0f; }

#pragma unroll
    for (int m = 0; m < 2; m++)
#pragma unroll
        for (int n = 0; n < 8; n++) {
            const int col  = n0w + n * 8 + tq * 2;
            const int row0 = m0w + m * 16 + g;
            const float v0 = acc[m][n][0], v1 = acc[m][n][1];
            const float v2 = acc[m][n][2], v3 = acc[m][n][3];
            *(__half2*)&A_s[row0 * ASTRIDE + col] = __floats2half2_rn(v0, v1);
            *(__half2*)&A_s[(row0 + 8) * ASTRIDE + col] = __floats2half2_rn(v2, v3);
            const float sa0 = sa[col], sa1 = sa[col + 1];
            const float da0 = da[col], da1 = da[col + 1];
            float t0 = tanh_fast(v0), t1 = tanh_fast(v1);
            float t2 = tanh_fast(v2), t3 = tanh_fast(v3);
            sp[m][0] = fmaf(t0, sa0, fmaf(t1, sa1, sp[m][0]));
            dp[m][0] = fmaf(t0, da0, fmaf(t1, da1, dp[m][0]));
            sp[m][1] = fmaf(t2, sa0, fmaf(t3, sa1, sp[m][1]));
            dp[m][1] = fmaf(t2, da0, fmaf(t3, da1, dp[m][1]));
        }
#pragma unroll
    for (int m = 0; m < 2; m++)
#pragma unroll
        for (int rh = 0; rh < 2; rh++) {
            float s = sp[m][rh], d = dp[m][rh];
            s += __shfl_xor_sync(0xffffffffu, s, 1);
            s += __shfl_xor_sync(0xffffffffu, s, 2);
            d += __shfl_xor_sync(0xffffffffu, d, 1);
            d += __shfl_xor_sync(0xffffffffu, d, 2);
            if (tq == 0) {
                const int row = m0w + m * 16 + g + rh * 8;
                redS[row * 2 + wn] = s;
                redD[row * 2 + wn] = d;
            }
        }
    __syncthreads();

    __half* hpo = g_hp16 + ((size_t)bh * NN + n0m) * FF;
#pragma unroll
    for (int it = 0; it < 8; it++) {
        int idx = tid + it * 256;
        int row = idx >> 4;
        int seg = (idx & 15) * 8;
        *(uint4*)&hpo[(size_t)row * FF + seg] =
            *(const uint4*)&A_s[row * ASTRIDE + seg];
    }
    if (tid < 128) {
        g_s[bh * NN + n0m + tid] = redS[tid * 2] + redS[tid * 2 + 1];
        g_d[bh * NN + n0m + tid] = redD[tid * 2] + redD[tid * 2 + 1];
    }
}

// ---------------- K3a: attention weights (packed {off, p half2}) -----------
__global__ __launch_bounds__(256) void attn_weights() {
    const int wg   = blockIdx.x * 8 + (threadIdx.x >> 5);
    const int lane = threadIdx.x & 31;
    const int h  = wg & 7;
    const int ri = wg >> 3;
    const int b  = ri >> 10;
    const int i  = ri & 1023;

    const int cnt = g_cnt[b * NN + i];
    const int* nb = &g_nbr[(b * NN + i) * MAXN];
    const float* dd = g_d + (b * HH + h) * NN;
    const float  si = g_s[(b * HH + h) * NN + i];
    uint2* ep = &g_ep[(size_t)((b * HH + h) * NN + i) * MAXN];

    float m = -1e30f;
    float scv[8];
    int   jv[8];
#pragma unroll
    for (int t = 0; t < 8; t++) {
        int k = lane + t * 32;
        float sc = -1e30f;
        int j = 0;
        if (k < cnt) {
            j = nb[k];
            sc = si + dd[j];
            sc = sc >= 0.0f ? sc : 0.2f * sc;
        }
        jv[t] = j;
        scv[t] = sc;
        m = fmaxf(m, sc);
    }
#pragma unroll
    for (int off = 16; off > 0; off >>= 1)
        m = fmaxf(m, __shfl_xor_sync(0xffffffffu, m, off));

    float ssum = 0.0f;
    float ev[8];
#pragma unroll
    for (int t = 0; t < 8; t++) {
        int k = lane + t * 32;
        float e = 0.0f;
        if (k < cnt) e = __expf(scv[t] - m);
        ev[t] = e;
        ssum += e;
    }
#pragma unroll
    for (int off = 16; off > 0; off >>= 1)
        ssum += __shfl_xor_sync(0xffffffffu, ssum, off);
    const float wsc = (1.0f / (float)HH) / ssum;

#pragma unroll
    for (int t = 0; t < 8; t++) {
        int k = lane + t * 32;
        if (k < cnt) {
            __half2 pp = __float2half2_rn(ev[t] * wsc);
            ep[k] = make_uint2((unsigned)((jv[t] & 511) << 8),
                               *(unsigned*)&pp);
        }
    }
}

// ---------------- K3b: half-owned fp16 smem gather (HFMA2 inner) -----------
__global__ __launch_bounds__(1024) void gat_gather() {
    extern __shared__ __align__(16) char hpb[];   // [512][128] fp16 = 128 KB
    const int q   = blockIdx.x;           // 0..1
    const int h   = blockIdx.y;
    const int b   = blockIdx.z;
    const int tid = threadIdx.x;
    const int w    = tid >> 5;
    const int lane = tid & 31;
    const int group = lane >> 4;
    const int gl    = lane & 15;
    const int bh  = b * HH + h;

    const __half* src = g_hp16 + ((size_t)bh * NN + q * 512) * FF;
#pragma unroll
    for (int it = 0; it < 8; it++) {
        int idx = tid + it * 1024;
        ((uint4*)hpb)[idx] = ((const uint4*)src)[idx];
    }
    __syncthreads();

    __half* po = g_po2h + ((size_t)q * BB * HH + bh) * NN * FF;
    const int gl16 = gl * 16;

#pragma unroll 1
    for (int ii = 0; ii < 16; ii++) {
        const int i = ii * 64 + w * 2 + group;
        const int4 qq = *(const int4*)&g_qoff[(b * NN + i) * 4];
        const int lo = q ? qq.y : 0;
        const int hi = q ? qq.w : qq.y;
        const uint2* ep = &g_ep[(size_t)(bh * NN + i) * MAXN];

        float a0 = 0.f, a1 = 0.f, a2 = 0.f, a3 = 0.f;
        float a4 = 0.f, a5 = 0.f, a6 = 0.f, a7 = 0.f;
        for (int k0 = lo; k0 < hi; k0 += 8) {
            uint2 r[8];
#pragma unroll
            for (int t = 0; t < 8; t++)
                r[t] = (k0 + t < hi) ? __ldg(ep + k0 + t)
                                     : make_uint2(0u, 0u);
            __half2 s0 = __floats2half2_rn(0.f, 0.f);
            __half2 s1 = s0, s2 = s0, s3 = s0;
#pragma unroll
            for (int t = 0; t < 8; t++) {
                const __half2 pp = *(const __half2*)&r[t].y;
                const uint4 hv = *(const uint4*)(hpb + r[t].x + gl16);
                s0 = __hfma2(*(const __half2*)&hv.x, pp, s0);
                s1 = __hfma2(*(const __half2*)&hv.y, pp, s1);
                s2 = __hfma2(*(const __half2*)&hv.z, pp, s2);
                s3 = __hfma2(*(const __half2*)&hv.w, pp, s3);
            }
            float2 f0 = __half22float2(s0);
            float2 f1 = __half22float2(s1);
            float2 f2 = __half22float2(s2);
            float2 f3 = __half22float2(s3);
            a0 += f0.x; a1 += f0.y; a2 += f1.x; a3 += f1.y;
            a4 += f2.x; a5 += f2.y; a6 += f3.x; a7 += f3.y;
        }
        uint4 outv;
        *(__half2*)&outv.x = __floats2half2_rn(a0, a1);
        *(__half2*)&outv.y = __floats2half2_rn(a2, a3);
        *(__half2*)&outv.z = __floats2half2_rn(a4, a5);
        *(__half2*)&outv.w = __floats2half2_rn(a6, a7);
        *(uint4*)&po[(size_t)i * FF + gl * 8] = outv;
    }
}

// ---------------- K3c: reduce partials + bias (+ReLU); fp32 + fp16 out -----
__global__ __launch_bounds__(256) void head_reduce(const float* __restrict__ bias,
                                                   float* __restrict__ xout,
                                                   int do_relu) {
    const int idx = blockIdx.x * 256 + threadIdx.x;
    const int ig  = idx >> 4;
    const int c8  = idx & 15;
    const int b   = ig >> 10;
    const int i   = ig & 1023;

    float a[8];
#pragma unroll
    for (int c = 0; c < 8; c++) a[c] = 0.0f;
#pragma unroll
    for (int qh = 0; qh < 2 * HH; qh++) {
        const int q = qh >> 3;
        const int h = qh & 7;
        const uint4 v = *(const uint4*)
            &g_po2h[(((size_t)q * BB * HH + b * HH + h) * NN + i) * FF + c8 * 8];
        float2 f0 = __half22float2(*(__half2*)&v.x);
        float2 f1 = __half22float2(*(__half2*)&v.y);
        float2 f2 = __half22float2(*(__half2*)&v.z);
        float2 f3 = __half22float2(*(__half2*)&v.w);
        a[0] += f0.x; a[1] += f0.y; a[2] += f1.x; a[3] += f1.y;
        a[4] += f2.x; a[5] += f2.y; a[6] += f3.x; a[7] += f3.y;
    }
    const float4 b0 = *(const float4*)&bias[c8 * 8];
    const float4 b1 = *(const float4*)&bias[c8 * 8 + 4];
    a[0] += b0.x; a[1] += b0.y; a[2] += b0.z; a[3] += b0.w;
    a[4] += b1.x; a[5] += b1.y; a[6] += b1.z; a[7] += b1.w;
    if (do_relu)
#pragma unroll
        for (int c = 0; c < 8; c++) a[c] = fmaxf(a[c], 0.0f);
    float* dst = &xout[(size_t)(b * NN + i) * FF + c8 * 8];
    *(float4*)dst       = make_float4(a[0], a[1], a[2], a[3]);
    *(float4*)(dst + 4) = make_float4(a[4], a[5], a[6], a[7]);
    // fp16 copy for next layer's GEMM staging
    uint4 hv;
    *(__half2*)&hv.x = __floats2half2_rn(a[0], a[1]);
    *(__half2*)&hv.y = __floats2half2_rn(a[2], a[3]);
    *(__half2*)&hv.z = __floats2half2_rn(a[4], a[5]);
    *(__half2*)&hv.w = __floats2half2_rn(a[6], a[7]);
    *(uint4*)&g_xh[(size_t)(b * NN + i) * FF + c8 * 8] = hv;
}

// ---------------- K4/K5: concat max-pool + linear --------------------------
__global__ __launch_bounds__(PRED_IN) void pool1() {
    const int chunk = blockIdx.x;
    const int b     = blockIdx.y;
    const int f     = threadIdx.x;
    const float* src; int fo;
    if (f < 128)       { src = g_x1; fo = f; }
    else if (f < 256)  { src = g_x2; fo = f - 128; }
    else               { src = g_x3; fo = f - 256; }
    src += (size_t)b * NN * FF + fo;
    const int n0 = chunk * 128;
    float m = -INFINITY;
#pragma unroll 8
    for (int n = 0; n < 128; n++)
        m = fmaxf(m, src[(size_t)(n0 + n) * FF]);
    g_pmax[(b * 8 + chunk) * PRED_IN + f] = m;
}

__global__ __launch_bounds__(PRED_IN) void pool2(const float* __restrict__ pw,
                                                 const float* __restrict__ pb,
                                                 float* __restrict__ out) {
    __shared__ float pooled[PRED_IN];
    const int b = blockIdx.x;
    const int f = threadIdx.x;
    float m = -INFINITY;
#pragma unroll
    for (int c = 0; c < 8; c++)
        m = fmaxf(m, g_pmax[(b * 8 + c) * PRED_IN + f]);
    pooled[f] = m;
    __syncthreads();
    if (f < LDIM) {
        float acc = pb[f];
        for (int k = 0; k < PRED_IN; k++)
            acc = fmaf(pooled[k], pw[k * LDIM + f], acc);
        out[b * LDIM + f] = acc;
    }
}

// ---------------- launch ----------------------------------------------------
extern "C" void kernel_launch(void* const* d_in, const int* in_sizes, int n_in,
                              void* d_out, int out_size) {
    const float* x   = (const float*)d_in[0];
    const float* adj = (const float*)d_in[1];
    const float* w1  = (const float*)d_in[2];
    const float* as1 = (const float*)d_in[3];
    const float* ad1 = (const float*)d_in[4];
    const float* b1  = (const float*)d_in[5];
    const float* w2  = (const float*)d_in[6];
    const float* as2 = (const float*)d_in[7];
    const float* ad2 = (const float*)d_in[8];
    const float* b2  = (const float*)d_in[9];
    const float* w3  = (const float*)d_in[10];
    const float* as3 = (const float*)d_in[11];
    const float* ad3 = (const float*)d_in[12];
    const float* b3  = (const float*)d_in[13];
    const float* pw  = (const float*)d_in[14];
    const float* pb  = (const float*)d_in[15];
    float* out = (float*)d_out;

    float* x1; cudaGetSymbolAddress((void**)&x1, g_x1);
    float* x2; cudaGetSymbolAddress((void**)&x2, g_x2);
    float* x3; cudaGetSymbolAddress((void**)&x3, g_x3);
    __half* xh; cudaGetSymbolAddress((void**)&xh, g_xh);
    __half* whp; cudaGetSymbolAddress((void**)&whp, g_wh);

    const int gsm  = 512 * FF * sizeof(__half);                 // 128 KB
    const int gemsm = 2 * 128 * ASTRIDE * 2 + 2 * 1024 + 1024;  // 72704 B
    static int smem_set = 0;
    if (!smem_set) {
        cudaFuncSetAttribute(gat_gather,
                             cudaFuncAttributeMaxDynamicSharedMemorySize, gsm);
        cudaFuncSetAttribute(gat_gemm,
                             cudaFuncAttributeMaxDynamicSharedMemorySize, gemsm);
        smem_set = 1;
    }

    const int WELEM = HH * FF * FF;

    // prep: fp16 conversions + neighbor lists
    conv_fp16<<<BB * NN * FF / 4 / 256, 256>>>(x, xh);
    conv_fp16<<<WELEM / 4 / 256, 256>>>(w1, whp);
    conv_fp16<<<WELEM / 4 / 256, 256>>>(w2, whp + WELEM);
    conv_fp16<<<WELEM / 4 / 256, 256>>>(w3, whp + 2 * WELEM);
    build_nbr<<<BB * NN / 8, 256>>>(adj);

    dim3 ggrid(64, HH);
    dim3 grgrid(2, HH, BB);
    const int wgrid = BB * NN * HH / 8;
    const int hrgrid = BB * NN * FF / 8 / 256;

    gat_gemm<<<ggrid, 256, gemsm>>>(whp, as1, ad1);
    attn_weights<<<wgrid, 256>>>();
    gat_gather<<<grgrid, 1024, gsm>>>();
    head_reduce<<<hrgrid, 256>>>(b1, x1, 1);

    gat_gemm<<<ggrid, 256, gemsm>>>(whp + WELEM, as2, ad2);
    attn_weights<<<wgrid, 256>>>();
    gat_gather<<<grgrid, 1024, gsm>>>();
    head_reduce<<<hrgrid, 256>>>(b2, x2, 1);

    gat_gemm<<<ggrid, 256, gemsm>>>(whp + 2 * WELEM, as3, ad3);
    attn_weights<<<wgrid, 256>>>();
    gat_gather<<<grgrid, 1024, gsm>>>();
    head_reduce<<<hrgrid, 256>>>(b3, x3, 0);

    pool1<<<dim3(8, BB), PRED_IN>>>();
    pool2<<<BB, PRED_IN>>>(pw, pb, out);
}